// round 14
// baseline (speedup 1.0000x reference)
#include <cuda_runtime.h>
#include <cuda_fp16.h>
#include <cstdint>

#define NV 8192
#define NC 128

// -------------------- device scratch (no allocs allowed) --------------------
__device__ __half g_Eh[(size_t)NV * NV];   // E fp16 (produced by GEMM1, used by GEMM2)
__device__ __half g_x[NV * NC];            // xw fp16
__device__ __half g_y[NV * NC];            // y  fp16
__device__ float g_part[2][NV * NC];       // split-K partials
__device__ float g_E0[64 * NC];
__device__ float g_E1[128 * NC];

// -------------------- small kernels ------------------------------------------
__global__ void coef_kernel(const float* __restrict__ ev0,
                            const float* __restrict__ ev1,
                            const float* __restrict__ dt) {
    int c = threadIdx.x;
    int b = blockIdx.x;
    if (b < 64) g_E0[b * NC + c] = __expf(-ev0[b] * dt[c]);
    else        g_E1[(b - 64) * NC + c] = __expf(-ev1[b - 64] * dt[NC + c]);
}

__device__ __forceinline__ uint32_t pack_h2(__half a, __half b) {
    __half2 p{a, b};
    return *(uint32_t*)&p;
}

// xw = x * mass -> fp16
__global__ void __launch_bounds__(256) prepx_kernel(const float4* __restrict__ x4,
                                                    const float* __restrict__ mass,
                                                    uint2* __restrict__ xq) {
    int idx = blockIdx.x * 256 + threadIdx.x;
    float m = mass[(idx * 4) >> 7];
    float4 v = x4[idx];
    xq[idx] = make_uint2(pack_h2(__float2half(v.x * m), __float2half(v.y * m)),
                         pack_h2(__float2half(v.z * m), __float2half(v.w * m)));
}

// reduce GEMM1 split-K partials, apply coef, emit fp16 y [V][C]
__global__ void __launch_bounds__(256) reduce1_kernel(const float4* __restrict__ P0,
                                                      const float4* __restrict__ P1,
                                                      uint2* __restrict__ y,
                                                      const float4* __restrict__ E0,
                                                      const float4* __restrict__ E1) {
    int idx = blockIdx.x * 256 + threadIdx.x;       // over NV*NC/4
    int gm = (idx * 4) >> 7;
    int gn4 = idx & 31;
    float4 a = P0[idx], b = P1[idx];
    float4 c0 = E0[(gm >> 7) * 32 + gn4];
    float4 c1 = E1[(gm & 127) * 32 + gn4];
    float v0 = (a.x + b.x) * c0.x * c1.x;
    float v1 = (a.y + b.y) * c0.y * c1.y;
    float v2 = (a.z + b.z) * c0.z * c1.z;
    float v3 = (a.w + b.w) * c0.w * c1.w;
    y[idx] = make_uint2(pack_h2(__float2half(v0), __float2half(v1)),
                        pack_h2(__float2half(v2), __float2half(v3)));
}

__global__ void __launch_bounds__(256) reduce2_kernel(const float4* __restrict__ P0,
                                                      const float4* __restrict__ P1,
                                                      float4* __restrict__ out) {
    int idx = blockIdx.x * 256 + threadIdx.x;
    float4 a = P0[idx], b = P1[idx];
    out[idx] = make_float4(a.x + b.x, a.y + b.y, a.z + b.z, a.w + b.w);
}

// -------------------- mma.sync helpers ----------------------------------------
__device__ __forceinline__ void ldsm4(uint32_t* r, uint32_t addr) {
    asm volatile("ldmatrix.sync.aligned.m8n8.x4.shared.b16 {%0,%1,%2,%3}, [%4];"
                 : "=r"(r[0]), "=r"(r[1]), "=r"(r[2]), "=r"(r[3]) : "r"(addr));
}
__device__ __forceinline__ void ldsm4t(uint32_t* r, uint32_t addr) {
    asm volatile("ldmatrix.sync.aligned.m8n8.x4.trans.shared.b16 {%0,%1,%2,%3}, [%4];"
                 : "=r"(r[0]), "=r"(r[1]), "=r"(r[2]), "=r"(r[3]) : "r"(addr));
}
__device__ __forceinline__ void mma16816(float* d, const uint32_t* a, const uint32_t* b) {
    asm volatile("mma.sync.aligned.m16n8k16.row.col.f32.f16.f16.f32 "
                 "{%0,%1,%2,%3}, {%4,%5,%6,%7}, {%8,%9}, {%0,%1,%2,%3};"
                 : "+f"(d[0]), "+f"(d[1]), "+f"(d[2]), "+f"(d[3])
                 : "r"(a[0]), "r"(a[1]), "r"(a[2]), "r"(a[3]),
                   "r"(b[0]), "r"(b[1]));
}
#define CP16(dst, src) \
    asm volatile("cp.async.cg.shared.global [%0], [%1], 16;" :: "r"(dst), "l"(src) : "memory")

// -------------------- GEMM config ----------------------------------------------
#define BM 64
#define BK 64
#define APAD 72                        // halves/row (144 B stride)
#define BPAD 136
#define A_BYTES  (BK * APAD * 2)       // 9216
#define B_BYTES  (BK * BPAD * 2)       // 17408

// ============ GEMM1 (fused E conversion): P = E^T @ xw, split-K =================
// A-path: LDG fp32 E -> regs -> cvt fp16 -> STS (smem tile) + STG (g_Eh).
// B-path: cp.async, 2-stage. A smem double-buffered.
// smem: A16[2] + B[2] = 2*9216 + 2*17408 = 53248 -> 2 CTAs/SM.
#define G1_SMEM (2 * A_BYTES + 2 * B_BYTES)

__global__ void __launch_bounds__(256, 2)
gemm1_kernel(const float* __restrict__ E, const __half* __restrict__ Bx,
             __half* __restrict__ EhOut, float* __restrict__ P)
{
    extern __shared__ char smraw[];
    const uint32_t smbase = (uint32_t)__cvta_generic_to_shared(smraw);
    const uint32_t Asm = smbase;                 // 2 x A_BYTES
    const uint32_t Bsm = smbase + 2 * A_BYTES;   // 2 x B_BYTES
    const int tid  = threadIdx.x;
    const int lane = tid & 31, wid = tid >> 5;
    const int wm   = wid >> 2, wn = wid & 3;     // 2 x 4 warps (32x32 tiles)
    const int m0   = blockIdx.x * BM;
    const int kbase = blockIdx.y * (NV / 2);
    float* Pout = P + (size_t)blockIdx.y * NV * NC;

    // conversion assignment: thread -> row r (k-dim), 16 m-contig floats at cb
    const int cr = tid >> 2;
    const int cb = (tid & 3) * 16;

    float4 abuf[4];
    auto ldgA = [&](int kt) {
        const float* src = E + (size_t)(kbase + kt * BK + cr) * NV + m0 + cb;
#pragma unroll
        for (int i = 0; i < 4; i++) abuf[i] = *(const float4*)(src + i * 4);
    };
    // convert regs -> fp16 smem stage s + STG to g_Eh
    auto stsA = [&](int kt, int s) {
        uint32_t h[8];
#pragma unroll
        for (int i = 0; i < 4; i++) {
            __half2 p0 = __floats2half2_rn(abuf[i].x, abuf[i].y);
            __half2 p1 = __floats2half2_rn(abuf[i].z, abuf[i].w);
            h[i * 2]     = *(uint32_t*)&p0;
            h[i * 2 + 1] = *(uint32_t*)&p1;
        }
        uint4 lo = make_uint4(h[0], h[1], h[2], h[3]);
        uint4 hi = make_uint4(h[4], h[5], h[6], h[7]);
        uint32_t so = Asm + s * A_BYTES + (uint32_t)(cr * APAD + cb) * 2;
        *(uint4*)(smraw + (so - smbase)) = lo;            // STS via generic (same smem)
        *(uint4*)(smraw + (so - smbase) + 16) = hi;
        uint4* gd = (uint4*)(EhOut + (size_t)(kbase + kt * BK + cr) * NV + m0 + cb);
        gd[0] = lo; gd[1] = hi;
    };
    auto issueB = [&](int kt, int s) {
        const int k0 = kbase + kt * BK;
        const uint32_t sb = Bsm + s * B_BYTES;
#pragma unroll
        for (int i = 0; i < 4; i++) {
            int idx = i * 256 + tid;
            int r = idx >> 4, q = idx & 15;
            size_t gb = (size_t)(k0 + r) * NC + q * 8;
            CP16(sb + (uint32_t)(r * BPAD + q * 8) * 2, (const void*)(Bx + gb));
        }
        asm volatile("cp.async.commit_group;" ::: "memory");
    };

    float acc[2][4][4];
#pragma unroll
    for (int a = 0; a < 2; a++)
#pragma unroll
        for (int b = 0; b < 4; b++)
#pragma unroll
            for (int q = 0; q < 4; q++) acc[a][b][q] = 0.0f;

    auto compute = [&](int s) {
        const uint32_t Ab = Asm + s * A_BYTES;
        const uint32_t Bb = Bsm + s * B_BYTES;
#pragma unroll
        for (int ks = 0; ks < 4; ks++) {
            uint32_t af[2][4], bf[2][4];
#pragma unroll
            for (int mi = 0; mi < 2; mi++) {
                int krow = ks * 16 + (lane & 7) + ((lane >> 4) << 3);
                int mcol = wm * 32 + mi * 16 + (lane & 8);
                ldsm4t(af[mi], Ab + (uint32_t)(krow * APAD + mcol) * 2);
            }
#pragma unroll
            for (int nj2 = 0; nj2 < 2; nj2++) {
                int krow = ks * 16 + (lane & 15);
                int ncol = wn * 32 + nj2 * 16 + ((lane >> 4) << 3);
                ldsm4t(bf[nj2], Bb + (uint32_t)(krow * BPAD + ncol) * 2);
            }
#pragma unroll
            for (int mi = 0; mi < 2; mi++)
#pragma unroll
                for (int nj = 0; nj < 4; nj++)
                    mma16816(acc[mi][nj], af[mi], &bf[nj >> 1][(nj & 1) * 2]);
        }
    };

    const int NIT = (NV / 2) / BK;   // 64
    ldgA(0);
    issueB(0, 0);
#pragma unroll 1
    for (int kt = 0; kt < NIT; kt++) {
        const int s = kt & 1;
        stsA(kt, s);                                   // convert + STS + STG
        if (kt + 1 < NIT) {
            ldgA(kt + 1);                              // prefetch next A (regs)
            issueB(kt + 1, (kt + 1) & 1);
            asm volatile("cp.async.wait_group 1;" ::: "memory");
        } else {
            asm volatile("cp.async.wait_group 0;" ::: "memory");
        }
        __syncthreads();                               // A16(s) + B(s) visible
        compute(s);
        __syncthreads();                               // protect buffers for next iter
    }

    // epilogue: fp32 partials
#pragma unroll
    for (int mi = 0; mi < 2; mi++) {
#pragma unroll
        for (int q = 0; q < 2; q++) {
            int gm = m0 + wm * 32 + mi * 16 + (lane >> 2) + q * 8;
#pragma unroll
            for (int nj = 0; nj < 4; nj++) {
                int gn = wn * 32 + nj * 8 + (lane & 3) * 2;
                *(float2*)&Pout[(size_t)gm * NC + gn] =
                    make_float2(acc[mi][nj][q * 2 + 0], acc[mi][nj][q * 2 + 1]);
            }
        }
    }
}

// ============ GEMM2: P = E @ y, split-K (unchanged from R13) =====================
#define STAGE_BYTES (A_BYTES + B_BYTES)
#define NSTAGE 3
#define G2_SMEM (NSTAGE * STAGE_BYTES)

__global__ void __launch_bounds__(256, 2)
gemm2_kernel(const __half* __restrict__ A, const __half* __restrict__ B,
             float* __restrict__ P)
{
    extern __shared__ __half sm[];
    const uint32_t smbase = (uint32_t)__cvta_generic_to_shared(sm);
    const int tid  = threadIdx.x;
    const int lane = tid & 31, wid = tid >> 5;
    const int wm   = wid >> 2, wn = wid & 3;
    const int m0   = blockIdx.x * BM;
    const int kbase = blockIdx.y * (NV / 2);
    float* Pout = P + (size_t)blockIdx.y * NV * NC;

    auto issue = [&](int kt, int s) {
        const int k0 = kbase + kt * BK;
        const uint32_t sb = smbase + s * STAGE_BYTES;
#pragma unroll
        for (int i = 0; i < 2; i++) {
            int idx = i * 256 + tid;
            int r = idx >> 3, q = idx & 7;
            size_t ga = (size_t)(m0 + r) * NV + k0 + q * 8;
            CP16(sb + (uint32_t)(r * APAD + q * 8) * 2, (const void*)(A + ga));
        }
#pragma unroll
        for (int i = 0; i < 4; i++) {
            int idx = i * 256 + tid;
            int r = idx >> 4, q = idx & 15;
            size_t gb = (size_t)(k0 + r) * NC + q * 8;
            CP16(sb + A_BYTES + (uint32_t)(r * BPAD + q * 8) * 2, (const void*)(B + gb));
        }
        asm volatile("cp.async.commit_group;" ::: "memory");
    };

    float acc[2][4][4];
#pragma unroll
    for (int a = 0; a < 2; a++)
#pragma unroll
        for (int b = 0; b < 4; b++)
#pragma unroll
            for (int q = 0; q < 4; q++) acc[a][b][q] = 0.0f;

    auto compute = [&](int s) {
        const uint32_t Ab = smbase + s * STAGE_BYTES;
        const uint32_t Bb = Ab + A_BYTES;
#pragma unroll
        for (int ks = 0; ks < 4; ks++) {
            uint32_t af[2][4], bf[2][4];
#pragma unroll
            for (int mi = 0; mi < 2; mi++) {
                int mrow = wm * 32 + mi * 16 + (lane & 15);
                int kcol = ks * 16 + ((lane >> 4) << 3);
                ldsm4(af[mi], Ab + (uint32_t)(mrow * APAD + kcol) * 2);
            }
#pragma unroll
            for (int nj2 = 0; nj2 < 2; nj2++) {
                int krow = ks * 16 + (lane & 15);
                int ncol = wn * 32 + nj2 * 16 + ((lane >> 4) << 3);
                ldsm4t(bf[nj2], Bb + (uint32_t)(krow * BPAD + ncol) * 2);
            }
#pragma unroll
            for (int mi = 0; mi < 2; mi++)
#pragma unroll
                for (int nj = 0; nj < 4; nj++)
                    mma16816(acc[mi][nj], af[mi], &bf[nj >> 1][(nj & 1) * 2]);
        }
    };

    const int NIT = (NV / 2) / BK;
    issue(0, 0);
    issue(1, 1);
#pragma unroll 1
    for (int kt = 0; kt < NIT; kt++) {
        if (kt < NIT - 1) asm volatile("cp.async.wait_group 1;" ::: "memory");
        else              asm volatile("cp.async.wait_group 0;" ::: "memory");
        __syncthreads();
        compute(kt % NSTAGE);
        if (kt + 2 < NIT) issue(kt + 2, (kt + 2) % NSTAGE);
    }

#pragma unroll
    for (int mi = 0; mi < 2; mi++) {
#pragma unroll
        for (int q = 0; q < 2; q++) {
            int gm = m0 + wm * 32 + mi * 16 + (lane >> 2) + q * 8;
#pragma unroll
            for (int nj = 0; nj < 4; nj++) {
                int gn = wn * 32 + nj * 8 + (lane & 3) * 2;
                *(float2*)&Pout[(size_t)gm * NC + gn] =
                    make_float2(acc[mi][nj][q * 2 + 0], acc[mi][nj][q * 2 + 1]);
            }
        }
    }
}

// -------------------- launch -----------------------------------------------------
// Inputs: 0:x[V,C] 1:edge_index 2:L 3:mass[V] 4:evals0[64] 5:evals1[128]
//         6:evecs[V,V] 7:diffusion_time[2,C]   Output: [V,C] fp32
extern "C" void kernel_launch(void* const* d_in, const int* in_sizes, int n_in,
                              void* d_out, int out_size) {
    const float* x      = (const float*)d_in[0];
    const float* mass   = (const float*)d_in[3];
    const float* evals0 = (const float*)d_in[4];
    const float* evals1 = (const float*)d_in[5];
    const float* evecs  = (const float*)d_in[6];
    const float* dt     = (const float*)d_in[7];
    float* out          = (float*)d_out;

    __half *Eh, *xq, *yq;
    float *P, *E0, *E1;
    cudaGetSymbolAddress((void**)&Eh, g_Eh);
    cudaGetSymbolAddress((void**)&xq, g_x);
    cudaGetSymbolAddress((void**)&yq, g_y);
    cudaGetSymbolAddress((void**)&P,  g_part);
    cudaGetSymbolAddress((void**)&E0, g_E0);
    cudaGetSymbolAddress((void**)&E1, g_E1);

    cudaFuncSetAttribute(gemm1_kernel, cudaFuncAttributeMaxDynamicSharedMemorySize, G1_SMEM);
    cudaFuncSetAttribute(gemm2_kernel, cudaFuncAttributeMaxDynamicSharedMemorySize, G2_SMEM);

    coef_kernel<<<192, 128>>>(evals0, evals1, dt);
    prepx_kernel<<<NV * NC / 4 / 256, 256>>>((const float4*)x, mass, (uint2*)xq);

    const int NQ = NV * NC / 4 / 256;
    // GEMM1: P = E^T @ xw (split-K), also emits g_Eh (fp16 E) as a side product
    gemm1_kernel<<<dim3(NV / BM, 2), 256, G1_SMEM>>>(evecs, xq, Eh, P);
    // y = coef .* (P0 + P1) -> fp16
    reduce1_kernel<<<NQ, 256>>>((const float4*)P, (const float4*)(P + NV * NC),
                                (uint2*)yq, (const float4*)E0, (const float4*)E1);
    // GEMM2: P = E @ y (split-K)
    gemm2_kernel<<<dim3(NV / BM, 2), 256, G2_SMEM>>>(Eh, yq, P);
    // out = P0 + P1
    reduce2_kernel<<<NQ, 256>>>((const float4*)P, (const float4*)(P + NV * NC), (float4*)out);
}

// round 15
// speedup vs baseline: 1.0128x; 1.0128x over previous
#include <cuda_runtime.h>
#include <cuda_fp16.h>
#include <cstdint>

#define NV 8192
#define NC 128

// -------------------- device scratch (no allocs allowed) --------------------
__device__ __half g_Eh[(size_t)NV * NV];   // E fp16, row-major
__device__ __half g_x[NV * NC];            // xw fp16
__device__ __half g_y[NV * NC];            // y  fp16
__device__ float g_P0[NV * NC];            // K-half-0 partials
__device__ float g_E0[64 * NC];
__device__ float g_E1[128 * NC];
__device__ int   g_flag[2][128];           // per-mtile handoff flags (self-resetting)

// -------------------- prep: coef tables + xw fp16 (merged) --------------------
__device__ __forceinline__ uint32_t pack_h2(__half a, __half b) {
    __half2 p{a, b};
    return *(uint32_t*)&p;
}

__global__ void __launch_bounds__(256) prep_kernel(const float4* __restrict__ x4,
                                                   const float* __restrict__ mass,
                                                   uint2* __restrict__ xq,
                                                   const float* __restrict__ ev0,
                                                   const float* __restrict__ ev1,
                                                   const float* __restrict__ dt) {
    int b = blockIdx.x;
    if (b < 1024) {
        int idx = b * 256 + threadIdx.x;
        float m = mass[(idx * 4) >> 7];
        float4 v = x4[idx];
        xq[idx] = make_uint2(pack_h2(__float2half(v.x * m), __float2half(v.y * m)),
                             pack_h2(__float2half(v.z * m), __float2half(v.w * m)));
    } else {
        int t = (b - 1024) * 256 + threadIdx.x;   // 96 blocks: 24576 = 8192 + 16384
        if (t < 64 * NC) {
            int i = t >> 7, c = t & 127;
            g_E0[t] = __expf(-ev0[i] * dt[c]);
        } else {
            int t2 = t - 64 * NC;
            int j = t2 >> 7, c = t2 & 127;
            g_E1[t2] = __expf(-ev1[j] * dt[NC + c]);
        }
    }
}

// E fp32 -> fp16, 8 values per thread, 16B stores
__global__ void __launch_bounds__(256) convE_kernel(const float4* __restrict__ E4,
                                                    uint4* __restrict__ Eh) {
    const size_t N8 = (size_t)NV * NV / 8;
    for (size_t idx = (size_t)blockIdx.x * 256 + threadIdx.x; idx < N8;
         idx += (size_t)gridDim.x * 256) {
        float4 a = E4[idx * 2], b = E4[idx * 2 + 1];
        Eh[idx] = make_uint4(pack_h2(__float2half(a.x), __float2half(a.y)),
                             pack_h2(__float2half(a.z), __float2half(a.w)),
                             pack_h2(__float2half(b.x), __float2half(b.y)),
                             pack_h2(__float2half(b.z), __float2half(b.w)));
    }
}

// -------------------- mma.sync helpers ----------------------------------------
__device__ __forceinline__ void ldsm4(uint32_t* r, uint32_t addr) {
    asm volatile("ldmatrix.sync.aligned.m8n8.x4.shared.b16 {%0,%1,%2,%3}, [%4];"
                 : "=r"(r[0]), "=r"(r[1]), "=r"(r[2]), "=r"(r[3]) : "r"(addr));
}
__device__ __forceinline__ void ldsm4t(uint32_t* r, uint32_t addr) {
    asm volatile("ldmatrix.sync.aligned.m8n8.x4.trans.shared.b16 {%0,%1,%2,%3}, [%4];"
                 : "=r"(r[0]), "=r"(r[1]), "=r"(r[2]), "=r"(r[3]) : "r"(addr));
}
__device__ __forceinline__ void mma16816(float* d, const uint32_t* a, const uint32_t* b) {
    asm volatile("mma.sync.aligned.m16n8k16.row.col.f32.f16.f16.f32 "
                 "{%0,%1,%2,%3}, {%4,%5,%6,%7}, {%8,%9}, {%0,%1,%2,%3};"
                 : "+f"(d[0]), "+f"(d[1]), "+f"(d[2]), "+f"(d[3])
                 : "r"(a[0]), "r"(a[1]), "r"(a[2]), "r"(a[3]),
                   "r"(b[0]), "r"(b[1]));
}
#define CP16(dst, src) \
    asm volatile("cp.async.cg.shared.global [%0], [%1], 16;" :: "r"(dst), "l"(src) : "memory")

// -------------------- GEMM config ----------------------------------------------
#define BM 64
#define BK 64
#define APAD 72                       // halves/row (144 B stride, mod128=16)
#define BPAD 136
#define A_BYTES  (BK * APAD * 2)      // 9216
#define B_BYTES  (BK * BPAD * 2)      // 17408
#define STAGE_BYTES (A_BYTES + B_BYTES)   // 26624
#define NSTAGE 3
#define SMEM_BYTES (NSTAGE * STAGE_BYTES) // 79872 -> 2 CTAs/SM (enforced below)

// Split-K GEMM with in-kernel cross-half reduction.
// blockIdx.x = M tile (128), blockIdx.y = K half (2). All 256 CTAs co-resident
// (launch_bounds(256,2)); half 0 publishes fp32 partials + flag, half 1 spins,
// adds, and finalizes (EPI=1: coef -> fp16 y; EPI=0: fp32 out).
// TRANS_A=1: Aop[m,k]=E[k,m] via ldmatrix.trans.
template <int TRANS_A, int EPI>
__global__ void __launch_bounds__(256, 2)
gemm_kernel(const __half* __restrict__ A, const __half* __restrict__ B,
            float* __restrict__ P0, int* __restrict__ flag,
            float* __restrict__ outF, __half* __restrict__ yout,
            const float* __restrict__ E0, const float* __restrict__ E1)
{
    extern __shared__ __half sm[];
    const uint32_t smbase = (uint32_t)__cvta_generic_to_shared(sm);
    const int tid  = threadIdx.x;
    const int lane = tid & 31, wid = tid >> 5;
    const int wm   = wid >> 2, wn = wid & 3;      // 2 x 4 warps (32x32 tiles)
    const int m0   = blockIdx.x * BM;
    const int half = blockIdx.y;
    const int kbase = half * (NV / 2);

    auto issue = [&](int kt, int s) {
        const int k0 = kbase + kt * BK;
        const uint32_t sb = smbase + s * STAGE_BYTES;
#pragma unroll
        for (int i = 0; i < 2; i++) {             // A: 512 chunks
            int idx = i * 256 + tid;
            int r = idx >> 3, q = idx & 7;
            size_t ga = TRANS_A ? (size_t)(k0 + r) * NV + m0 + q * 8
                                : (size_t)(m0 + r) * NV + k0 + q * 8;
            CP16(sb + (uint32_t)(r * APAD + q * 8) * 2, (const void*)(A + ga));
        }
#pragma unroll
        for (int i = 0; i < 4; i++) {             // B: 1024 chunks
            int idx = i * 256 + tid;
            int r = idx >> 4, q = idx & 15;
            size_t gb = (size_t)(k0 + r) * NC + q * 8;
            CP16(sb + A_BYTES + (uint32_t)(r * BPAD + q * 8) * 2, (const void*)(B + gb));
        }
        asm volatile("cp.async.commit_group;" ::: "memory");
    };

    float acc[2][4][4];
#pragma unroll
    for (int a = 0; a < 2; a++)
#pragma unroll
        for (int b = 0; b < 4; b++)
#pragma unroll
            for (int q = 0; q < 4; q++) acc[a][b][q] = 0.0f;

    auto compute = [&](int s) {
        const uint32_t Ab = smbase + s * STAGE_BYTES;
        const uint32_t Bb = Ab + A_BYTES;
#pragma unroll
        for (int ks = 0; ks < 4; ks++) {
            uint32_t af[2][4], bf[2][4];
#pragma unroll
            for (int mi = 0; mi < 2; mi++) {
                if (TRANS_A) {
                    int krow = ks * 16 + (lane & 7) + ((lane >> 4) << 3);
                    int mcol = wm * 32 + mi * 16 + (lane & 8);
                    ldsm4t(af[mi], Ab + (uint32_t)(krow * APAD + mcol) * 2);
                } else {
                    int mrow = wm * 32 + mi * 16 + (lane & 15);
                    int kcol = ks * 16 + ((lane >> 4) << 3);
                    ldsm4(af[mi], Ab + (uint32_t)(mrow * APAD + kcol) * 2);
                }
            }
#pragma unroll
            for (int nj2 = 0; nj2 < 2; nj2++) {
                int krow = ks * 16 + (lane & 15);
                int ncol = wn * 32 + nj2 * 16 + ((lane >> 4) << 3);
                ldsm4t(bf[nj2], Bb + (uint32_t)(krow * BPAD + ncol) * 2);
            }
#pragma unroll
            for (int mi = 0; mi < 2; mi++)
#pragma unroll
                for (int nj = 0; nj < 4; nj++)
                    mma16816(acc[mi][nj], af[mi], &bf[nj >> 1][(nj & 1) * 2]);
        }
    };

    const int NIT = (NV / 2) / BK;   // 64
    issue(0, 0);
    issue(1, 1);
#pragma unroll 1
    for (int kt = 0; kt < NIT; kt++) {
        if (kt < NIT - 1) asm volatile("cp.async.wait_group 1;" ::: "memory");
        else              asm volatile("cp.async.wait_group 0;" ::: "memory");
        __syncthreads();
        compute(kt % NSTAGE);
        if (kt + 2 < NIT) issue(kt + 2, (kt + 2) % NSTAGE);
    }

    // ---- epilogue with cross-half handoff ----
    if (half == 0) {
#pragma unroll
        for (int mi = 0; mi < 2; mi++)
#pragma unroll
            for (int q = 0; q < 2; q++) {
                int gm = m0 + wm * 32 + mi * 16 + (lane >> 2) + q * 8;
#pragma unroll
                for (int nj = 0; nj < 4; nj++) {
                    int gn = wn * 32 + nj * 8 + (lane & 3) * 2;
                    *(float2*)&P0[(size_t)gm * NC + gn] =
                        make_float2(acc[mi][nj][q * 2 + 0], acc[mi][nj][q * 2 + 1]);
                }
            }
        __threadfence();
        __syncthreads();
        if (tid == 0) atomicExch(&flag[blockIdx.x], 1);
    } else {
        if (tid == 0) {
            while (atomicAdd(&flag[blockIdx.x], 0) == 0) __nanosleep(64);
        }
        __syncthreads();
        __threadfence();
#pragma unroll
        for (int mi = 0; mi < 2; mi++)
#pragma unroll
            for (int q = 0; q < 2; q++) {
                int gm = m0 + wm * 32 + mi * 16 + (lane >> 2) + q * 8;
                int i0 = gm >> 7, i1 = gm & 127;
#pragma unroll
                for (int nj = 0; nj < 4; nj++) {
                    int gn = wn * 32 + nj * 8 + (lane & 3) * 2;
                    float2 p = *(const float2*)&P0[(size_t)gm * NC + gn];
                    float v0 = acc[mi][nj][q * 2 + 0] + p.x;
                    float v1 = acc[mi][nj][q * 2 + 1] + p.y;
                    if (EPI) {
                        v0 *= E0[i0 * NC + gn]     * E1[i1 * NC + gn];
                        v1 *= E0[i0 * NC + gn + 1] * E1[i1 * NC + gn + 1];
                        *(uint32_t*)&yout[(size_t)gm * NC + gn] =
                            pack_h2(__float2half(v0), __float2half(v1));
                    } else {
                        *(float2*)&outF[(size_t)gm * NC + gn] = make_float2(v0, v1);
                    }
                }
            }
        __syncthreads();
        if (tid == 0) atomicExch(&flag[blockIdx.x], 0);   // reset for next replay
    }
}

// -------------------- launch -----------------------------------------------------
// Inputs: 0:x[V,C] 1:edge_index 2:L 3:mass[V] 4:evals0[64] 5:evals1[128]
//         6:evecs[V,V] 7:diffusion_time[2,C]   Output: [V,C] fp32
extern "C" void kernel_launch(void* const* d_in, const int* in_sizes, int n_in,
                              void* d_out, int out_size) {
    const float* x      = (const float*)d_in[0];
    const float* mass   = (const float*)d_in[3];
    const float* evals0 = (const float*)d_in[4];
    const float* evals1 = (const float*)d_in[5];
    const float* evecs  = (const float*)d_in[6];
    const float* dt     = (const float*)d_in[7];
    float* out          = (float*)d_out;

    __half *Eh, *xq, *yq;
    float *P0, *E0, *E1;
    int *flags;
    cudaGetSymbolAddress((void**)&Eh,    g_Eh);
    cudaGetSymbolAddress((void**)&xq,    g_x);
    cudaGetSymbolAddress((void**)&yq,    g_y);
    cudaGetSymbolAddress((void**)&P0,    g_P0);
    cudaGetSymbolAddress((void**)&E0,    g_E0);
    cudaGetSymbolAddress((void**)&E1,    g_E1);
    cudaGetSymbolAddress((void**)&flags, g_flag);

    cudaFuncSetAttribute(gemm_kernel<1, 1>, cudaFuncAttributeMaxDynamicSharedMemorySize, SMEM_BYTES);
    cudaFuncSetAttribute(gemm_kernel<0, 0>, cudaFuncAttributeMaxDynamicSharedMemorySize, SMEM_BYTES);

    prep_kernel<<<1120, 256>>>((const float4*)x, mass, (uint2*)xq, evals0, evals1, dt);
    convE_kernel<<<2368, 256>>>((const float4*)evecs, (uint4*)Eh);

    // GEMM1: y = coef .* (E^T @ xw)  (split-K, in-kernel reduction)
    gemm_kernel<1, 1><<<dim3(NV / BM, 2), 256, SMEM_BYTES>>>(
        Eh, xq, P0, flags, nullptr, yq, E0, E1);
    // GEMM2: out = E @ y  (split-K, in-kernel reduction)
    gemm_kernel<0, 0><<<dim3(NV / BM, 2), 256, SMEM_BYTES>>>(
        Eh, yq, P0, flags + 128, out, nullptr, nullptr, nullptr);
}